// round 13
// baseline (speedup 1.0000x reference)
#include <cuda_runtime.h>
#include <cuda_fp16.h>
#include <cstdint>

#define DEVINL __device__ __forceinline__

// ---------------- problem constants ----------------
constexpr int B_   = 65536;
constexpr int DIN  = 256;
constexpr int H_   = 512;
constexpr int KTOT = DIN + H_;     // 768
constexpr int NTOT = 4 * H_;       // 2048 packed gate columns
constexpr int BM   = 128;
constexpr int BN   = 256;
constexpr int BKH  = 64;           // k-slice in halves (128 B/row)
constexpr int NIT  = KTOT / BKH;   // 12
constexpr int GN   = NTOT / BN;    // 8
constexpr int GM   = B_ / BM;      // 512
constexpr int NTH  = 256;          // 8 warps: 2 (m) x 4 (n), warp tile 64x64
constexpr long long BH = (long long)B_ * H_;

// smem per stage: A 128x128B = 16K, B 256x128B = 32K
constexpr uint32_t STG_A = 16384;
constexpr uint32_t STG   = 49152;
constexpr uint32_t SMEM_BYTES = 2 * STG;      // 98304 -> 2 CTAs/SM (192 KB)
// epilogue gate quarter-buffer (32 KB) lives in stage 0; last compute reads stage 1.

// ---------------- device scratch ----------------
__device__ __half g_Ah[(size_t)B_ * KTOT];   // [b][k] packed [x|h] halves (96 MB)
__device__ __half g_Wth[NTOT * KTOT];        // [n'][k] halves, K contiguous
__device__ float  g_bias[NTOT];

// ---------------- helpers ----------------
DEVINL uint32_t smem_u32(const void* p) {
    uint32_t a;
    asm("{ .reg .u64 t; cvta.to.shared.u64 t, %1; cvt.u32.u64 %0, t; }" : "=r"(a) : "l"(p));
    return a;
}
DEVINL float tanh_fast(float x) { float y; asm("tanh.approx.f32 %0, %1;" : "=f"(y) : "f"(x)); return y; }
DEVINL float sig_fast(float x)  { return fmaf(tanh_fast(0.5f * x), 0.5f, 0.5f); }

DEVINL void ldsm4(uint32_t* r, uint32_t addr) {
    asm volatile("ldmatrix.sync.aligned.m8n8.x4.shared.b16 {%0,%1,%2,%3}, [%4];"
                 : "=r"(r[0]), "=r"(r[1]), "=r"(r[2]), "=r"(r[3]) : "r"(addr));
}
// fp16-accumulate MMA (2x fp32-accum rate on the legacy pipe)
DEVINL void mma16816h(uint32_t* d, const uint32_t* a, const uint32_t* b) {
    asm volatile("mma.sync.aligned.m16n8k16.row.col.f16.f16.f16.f16 "
                 "{%0,%1}, {%2,%3,%4,%5}, {%6,%7}, {%0,%1};"
                 : "+r"(d[0]), "+r"(d[1])
                 : "r"(a[0]), "r"(a[1]), "r"(a[2]), "r"(a[3]), "r"(b[0]), "r"(b[1]));
}
DEVINL void cpasync16(uint32_t dst, const void* src) {
    asm volatile("cp.async.cg.shared.global [%0], [%1], 16;" :: "r"(dst), "l"(src) : "memory");
}
#define CP_COMMIT() asm volatile("cp.async.commit_group;" ::: "memory")
DEVINL uint32_t h2u(__half2 h) { return *reinterpret_cast<uint32_t*>(&h); }
DEVINL void sts_v2f(uint32_t addr, float a, float b) {
    asm volatile("st.shared.v2.f32 [%0], {%1,%2};" :: "r"(addr), "f"(a), "f"(b) : "memory");
}
DEVINL float4 lds_v4f(uint32_t addr) {
    float4 v;
    asm volatile("ld.shared.v4.f32 {%0,%1,%2,%3}, [%4];"
                 : "=f"(v.x), "=f"(v.y), "=f"(v.z), "=f"(v.w) : "r"(addr));
    return v;
}

// packed column index -> (h, g):  n' = (h>>2)*16 + g*4 + (h&3)
DEVINL void unpack_np(int np, int& h, int& g) {
    int Q = np >> 4, wi = np & 15;
    g = wi >> 2;
    h = (Q << 2) | (wi & 3);
}

// gate-smem swizzled address, quarter buffer: (row 0..31, col c 0..255), fp32,
// 1024B row stride. Proven conflict-free (R9/R10) for STS.64 and LDS.128.
DEVINL uint32_t gaddr(int row, int c) {
    int u = c >> 2;
    int q = u >> 2, j = u & 3;
    int us = (4 * q + (j ^ (q & 3) ^ ((q >> 2) & 3))) ^ (row & 7);
    return (uint32_t)(row * 1024 + us * 16 + (c & 3) * 4);
}

// ---------------- unified pack kernel ----------------
constexpr int ACH = B_ * (KTOT / 8);          // A 16B-chunks
constexpr int WCH = (NTOT * KTOT) / 8;        // W 16B-chunks
constexpr int PACK_TOTAL = ACH + WCH + NTOT;  // + bias
__global__ void lstm_pack(const float* __restrict__ U, const float* __restrict__ bU,
                          const float* __restrict__ W, const float* __restrict__ bW,
                          const float* __restrict__ X, const float* __restrict__ Hold) {
    int t = blockIdx.x * 256 + threadIdx.x;
    if (t < ACH) {
        int b  = t / (KTOT / 8);
        int k0 = (t - b * (KTOT / 8)) * 8;
        const float* src = (k0 < DIN) ? (X + (size_t)b * DIN + k0)
                                      : (Hold + (size_t)b * H_ + (k0 - DIN));
        float4 v0 = __ldg((const float4*)src);
        float4 v1 = __ldg((const float4*)(src + 4));
        uint4 o;
        o.x = h2u(__floats2half2_rn(v0.x, v0.y));
        o.y = h2u(__floats2half2_rn(v0.z, v0.w));
        o.z = h2u(__floats2half2_rn(v1.x, v1.y));
        o.w = h2u(__floats2half2_rn(v1.z, v1.w));
        *(uint4*)(g_Ah + (size_t)b * KTOT + k0) = o;
    } else if (t < ACH + WCH) {
        int c0 = (t - ACH) * 8;
        int np = c0 / KTOT;
        int k0 = c0 - np * KTOT;
        int h, g; unpack_np(np, h, g);
        __half o[8];
        #pragma unroll
        for (int j = 0; j < 8; ++j) {
            int k = k0 + j;
            float v = (k < DIN) ? U[(g * DIN + k) * H_ + h]
                                : W[(g * H_ + (k - DIN)) * H_ + h];
            o[j] = __float2half_rn(v);
        }
        *(uint4*)(g_Wth + c0) = *(const uint4*)o;
    } else if (t < PACK_TOTAL) {
        int np = t - ACH - WCH;
        int h, g; unpack_np(np, h, g);
        g_bias[np] = bU[g * H_ + h] + bW[g * H_ + h];
    }
}

// ---------------- main fused kernel: 128x256 CTA, warp tile 64x64, 2 CTAs/SM ----------------
__global__ void __launch_bounds__(NTH, 2)
lstm_mma_kernel(const float* __restrict__ Cold, float* __restrict__ out) {
    extern __shared__ char smem[];
    const uint32_t sb = smem_u32(smem);
    const int tid = threadIdx.x;
    const int wid = tid >> 5, l = tid & 31;
    const int s = l & 7;
    const int hi4 = l >> 4;
    const int hi3 = (l >> 3) & 1;

    const int m0 = (int)(blockIdx.x >> 3) * BM;   // n-fastest for A L2 reuse
    const int n0 = (int)(blockIdx.x & 7) * BN;
    const int wm = wid >> 2, wn = wid & 3;        // 2 x 4 warps, each 64(m) x 64(n)

    // ---- ldmatrix row-base addresses + precomputed per-kc offsets ----
    uint32_t a_ld[4], b_ld[4], aoffs[4], boffs[4];
    #pragma unroll
    for (int mf = 0; mf < 4; ++mf)
        a_ld[mf] = sb + (uint32_t)((wm * 64 + mf * 16 + (l & 15)) * 128);
    #pragma unroll
    for (int p = 0; p < 4; ++p)
        b_ld[p] = sb + STG_A + (uint32_t)((wn * 64 + p * 16 + hi4 * 8 + (l & 7)) * 128);
    #pragma unroll
    for (int kc = 0; kc < 4; ++kc) {
        aoffs[kc] = (uint32_t)(((2 * kc + hi4) ^ s) << 4);
        boffs[kc] = (uint32_t)(((2 * kc + hi3) ^ s) << 4);
    }

    // ---- staging constants (256 threads) ----
    const int ar  = tid >> 1;            // A row 0..127, 2 threads/row
    const int ac0 = (tid & 1) * 4;       // 4 chunks of 16B each
    const int br  = tid;                 // B row 0..255, 1 thread/row, 8 chunks
    uint32_t a_sdst[4], b_sdst[8];
    #pragma unroll
    for (int j = 0; j < 4; ++j)
        a_sdst[j] = sb + (uint32_t)ar * 128u + (uint32_t)(((ac0 + j) ^ (ar & 7)) << 4);
    #pragma unroll
    for (int j = 0; j < 8; ++j)
        b_sdst[j] = sb + STG_A + (uint32_t)br * 128u + (uint32_t)((j ^ (br & 7)) << 4);
    const __half* a_srcb = g_Ah  + (size_t)(m0 + ar) * KTOT + ac0 * 8;
    const __half* b_srcb = g_Wth + (size_t)(n0 + br) * KTOT;

    auto stage = [&](uint32_t so, int it) {
        const __half* as = a_srcb + it * BKH;   // constant-folds under full unroll
        const __half* bs = b_srcb + it * BKH;
        #pragma unroll
        for (int j = 0; j < 4; ++j) cpasync16(a_sdst[j] + so, as + j * 8);
        #pragma unroll
        for (int j = 0; j < 8; ++j) cpasync16(b_sdst[j] + so, bs + j * 8);
        CP_COMMIT();
    };

    // ---- accumulators: fp16x2, [mf][nj][row-group] ----
    uint32_t C[4][8][2];
    #pragma unroll
    for (int mf = 0; mf < 4; ++mf)
        #pragma unroll
        for (int nj = 0; nj < 8; ++nj) { C[mf][nj][0] = 0u; C[mf][nj][1] = 0u; }

    auto compute = [&](uint32_t so) {
        #pragma unroll
        for (int kc = 0; kc < 4; ++kc) {
            uint32_t afr[4][4], bfr[4][4];
            #pragma unroll
            for (int mf = 0; mf < 4; ++mf) ldsm4(afr[mf], a_ld[mf] + so + aoffs[kc]);
            #pragma unroll
            for (int p = 0; p < 4; ++p)    ldsm4(bfr[p], b_ld[p] + so + boffs[kc]);
            #pragma unroll
            for (int mf = 0; mf < 4; ++mf)
                #pragma unroll
                for (int nj = 0; nj < 8; ++nj)
                    mma16816h(C[mf][nj], afr[mf], &bfr[nj >> 1][(nj & 1) * 2]);
        }
    };

    // ---- fully-unrolled 2-stage pipeline ----
    stage(0, 0);
    #pragma unroll
    for (int it = 0; it < NIT; ++it) {
        asm volatile("cp.async.wait_group 0;" ::: "memory");
        __syncthreads();   // (a) tile `it` visible; (b) compute(it-1) reads done
        if (it + 1 < NIT) stage(((it + 1) & 1) ? STG : 0u, it + 1);
        compute((it & 1) ? STG : 0u);
    }

    // ---- epilogue: four 32-row quarters through stage-0 smem (32 KB) ----
    // safe: last compute (it=11) reads stage 1 = [49152, 98304) only.
    const int q    = l & 3;
    const int quad = tid & 15;          // h-quad within CTA (16 quads = 64 h)
    const int r0   = tid >> 4;          // 0..15
    const int h0   = (n0 >> 2) + quad * 4;
    const int cb   = quad * 16;         // gate cols: [i x4, f x4, o x4, c x4]

    const float4 bi = __ldg((const float4*)(g_bias + n0 + cb));
    const float4 bf = __ldg((const float4*)(g_bias + n0 + cb + 4));
    const float4 bo = __ldg((const float4*)(g_bias + n0 + cb + 8));
    const float4 bc = __ldg((const float4*)(g_bias + n0 + cb + 12));

    #pragma unroll
    for (int qtr = 0; qtr < 4; ++qtr) {
        if (qtr) __syncthreads();       // previous quarter's pass-2 reads done
        // pass 1: owner warps (wm == qtr>>1) dump frags mf = 2*(qtr&1)+{0,1}
        if (wm == (qtr >> 1)) {
            #pragma unroll
            for (int mfl = 0; mfl < 2; ++mfl) {
                const int mf = 2 * (qtr & 1) + mfl;
                #pragma unroll
                for (int nj = 0; nj < 8; ++nj) {
                    const int cbase = wn * 64 + nj * 8 + 2 * q;
                    #pragma unroll
                    for (int dp = 0; dp < 2; ++dp) {
                        const int row = mfl * 16 + dp * 8 + (l >> 2);   // 0..31
                        float2 v = __half22float2(*reinterpret_cast<const __half2*>(&C[mf][nj][dp]));
                        sts_v2f(sb + gaddr(row, cbase), v.x, v.y);
                    }
                }
            }
        }
        __syncthreads();

        // pass 2: 256 threads fuse 32 rows x 64 h (2 rows each)
        #pragma unroll
        for (int p = 0; p < 2; ++p) {
            const int row = r0 + p * 16;                  // 0..31 within quarter
            const long long b = m0 + qtr * 32 + row;

            float4 gi = lds_v4f(sb + gaddr(row, cb));
            float4 gf = lds_v4f(sb + gaddr(row, cb + 4));
            float4 go = lds_v4f(sb + gaddr(row, cb + 8));
            float4 gc = lds_v4f(sb + gaddr(row, cb + 12));
            float4 co = __ldg((const float4*)(Cold + b * H_ + h0));

            float4 hn, cn;
            {
                float i_ = sig_fast(gi.x + bi.x), f_ = sig_fast(gf.x + bf.x);
                float o_ = sig_fast(go.x + bo.x), ct = tanh_fast(gc.x + bc.x);
                cn.x = fmaf(i_, ct, f_ * co.x);  hn.x = o_ * tanh_fast(cn.x);
            }
            {
                float i_ = sig_fast(gi.y + bi.y), f_ = sig_fast(gf.y + bf.y);
                float o_ = sig_fast(go.y + bo.y), ct = tanh_fast(gc.y + bc.y);
                cn.y = fmaf(i_, ct, f_ * co.y);  hn.y = o_ * tanh_fast(cn.y);
            }
            {
                float i_ = sig_fast(gi.z + bi.z), f_ = sig_fast(gf.z + bf.z);
                float o_ = sig_fast(go.z + bo.z), ct = tanh_fast(gc.z + bc.z);
                cn.z = fmaf(i_, ct, f_ * co.z);  hn.z = o_ * tanh_fast(cn.z);
            }
            {
                float i_ = sig_fast(gi.w + bi.w), f_ = sig_fast(gf.w + bf.w);
                float o_ = sig_fast(go.w + bo.w), ct = tanh_fast(gc.w + bc.w);
                cn.w = fmaf(i_, ct, f_ * co.w);  hn.w = o_ * tanh_fast(cn.w);
            }

            *(float4*)(out + b * H_ + h0)      = hn;
            *(float4*)(out + BH + b * H_ + h0) = cn;
        }
    }
}

// ---------------- harness entry ----------------
extern "C" void kernel_launch(void* const* d_in, const int* in_sizes, int n_in,
                              void* d_out, int out_size) {
    const float* X    = (const float*)d_in[0];  // input_x [B, 256]
    const float* Hold = (const float*)d_in[1];  // h_old   [B, 512]
    const float* Cold = (const float*)d_in[2];  // c_old   [B, 512]
    const float* U    = (const float*)d_in[3];  // [4, 256, 512]
    const float* bU   = (const float*)d_in[4];  // [4, 512]
    const float* W    = (const float*)d_in[5];  // [4, 512, 512]
    const float* bW   = (const float*)d_in[6];  // [4, 512]
    float* out = (float*)d_out;                 // [h_new | c_new]
    (void)in_sizes; (void)n_in; (void)out_size;

    lstm_pack<<<(PACK_TOTAL + 255) / 256, 256>>>(U, bU, W, bW, X, Hold);

    cudaFuncSetAttribute(lstm_mma_kernel,
                         cudaFuncAttributeMaxDynamicSharedMemorySize, SMEM_BYTES);
    lstm_mma_kernel<<<GM * GN, NTH, SMEM_BYTES>>>(Cold, out);
}

// round 15
// speedup vs baseline: 1.3390x; 1.3390x over previous
#include <cuda_runtime.h>
#include <cuda_fp16.h>
#include <cstdint>

#define DEVINL __device__ __forceinline__

// ---------------- problem constants ----------------
constexpr int B_   = 65536;
constexpr int DIN  = 256;
constexpr int H_   = 512;
constexpr int KTOT = DIN + H_;     // 768
constexpr int NTOT = 4 * H_;       // 2048 packed gate columns
constexpr int BM   = 128;
constexpr int BN   = 256;
constexpr int BKH  = 64;           // k-slice in halves (128 B/row)
constexpr int NIT  = KTOT / BKH;   // 12
constexpr int GN   = NTOT / BN;    // 8
constexpr int GM   = B_ / BM;      // 512
constexpr int NTH  = 512;          // 16 warps: 2 (m) x 8 (n), warp tile 64x32
constexpr long long BH = (long long)B_ * H_;

// smem per stage: A 128x128B = 16K, B 256x128B = 32K
constexpr uint32_t STG_A = 16384;
constexpr uint32_t STG   = 49152;
constexpr uint32_t SMEM_BYTES = 2 * STG;      // 98304 -> 2 CTAs/SM (192 KB)
// epilogue gate quarter-buffer (32 KB) lives in stage 0; last compute reads stage 1.

// ---------------- device scratch ----------------
__device__ __half g_Ah[(size_t)B_ * KTOT];   // [b][k] packed [x|h] halves (96 MB)
__device__ __half g_Wth[NTOT * KTOT];        // [n'][k] halves, K contiguous
__device__ float  g_bias[NTOT];

// ---------------- helpers ----------------
DEVINL uint32_t smem_u32(const void* p) {
    uint32_t a;
    asm("{ .reg .u64 t; cvta.to.shared.u64 t, %1; cvt.u32.u64 %0, t; }" : "=r"(a) : "l"(p));
    return a;
}
DEVINL float tanh_fast(float x) { float y; asm("tanh.approx.f32 %0, %1;" : "=f"(y) : "f"(x)); return y; }
DEVINL float sig_fast(float x)  { return fmaf(tanh_fast(0.5f * x), 0.5f, 0.5f); }

DEVINL void ldsm4(uint32_t* r, uint32_t addr) {
    asm volatile("ldmatrix.sync.aligned.m8n8.x4.shared.b16 {%0,%1,%2,%3}, [%4];"
                 : "=r"(r[0]), "=r"(r[1]), "=r"(r[2]), "=r"(r[3]) : "r"(addr));
}
// fp16-accumulate MMA (2x fp32-accum rate on the legacy pipe)
DEVINL void mma16816h(uint32_t* d, const uint32_t* a, const uint32_t* b) {
    asm volatile("mma.sync.aligned.m16n8k16.row.col.f16.f16.f16.f16 "
                 "{%0,%1}, {%2,%3,%4,%5}, {%6,%7}, {%0,%1};"
                 : "+r"(d[0]), "+r"(d[1])
                 : "r"(a[0]), "r"(a[1]), "r"(a[2]), "r"(a[3]), "r"(b[0]), "r"(b[1]));
}
DEVINL void cpasync16(uint32_t dst, const void* src) {
    asm volatile("cp.async.cg.shared.global [%0], [%1], 16;" :: "r"(dst), "l"(src) : "memory");
}
#define CP_COMMIT() asm volatile("cp.async.commit_group;" ::: "memory")
DEVINL uint32_t h2u(__half2 h) { return *reinterpret_cast<uint32_t*>(&h); }
DEVINL void sts_v2f(uint32_t addr, float a, float b) {
    asm volatile("st.shared.v2.f32 [%0], {%1,%2};" :: "r"(addr), "f"(a), "f"(b) : "memory");
}
DEVINL float4 lds_v4f(uint32_t addr) {
    float4 v;
    asm volatile("ld.shared.v4.f32 {%0,%1,%2,%3}, [%4];"
                 : "=f"(v.x), "=f"(v.y), "=f"(v.z), "=f"(v.w) : "r"(addr));
    return v;
}

// packed column index -> (h, g):  n' = (h>>2)*16 + g*4 + (h&3)
DEVINL void unpack_np(int np, int& h, int& g) {
    int Q = np >> 4, wi = np & 15;
    g = wi >> 2;
    h = (Q << 2) | (wi & 3);
}

// gate-smem swizzled address, quarter buffer: (row 0..31, col c 0..255), fp32,
// 1024B row stride. Conflict-free for pass-1 STS.64 and pass-2 LDS.128 (proven R9/R10).
DEVINL uint32_t gaddr(int row, int c) {
    int u = c >> 2;
    int q = u >> 2, j = u & 3;
    int us = (4 * q + (j ^ (q & 3) ^ ((q >> 2) & 3))) ^ (row & 7);
    return (uint32_t)(row * 1024 + us * 16 + (c & 3) * 4);
}

// ---------------- unified pack kernel ----------------
constexpr int ACH = B_ * (KTOT / 8);          // A 16B-chunks
constexpr int WCH = (NTOT * KTOT) / 8;        // W 16B-chunks
constexpr int PACK_TOTAL = ACH + WCH + NTOT;  // + bias
__global__ void lstm_pack(const float* __restrict__ U, const float* __restrict__ bU,
                          const float* __restrict__ W, const float* __restrict__ bW,
                          const float* __restrict__ X, const float* __restrict__ Hold) {
    int t = blockIdx.x * 256 + threadIdx.x;
    if (t < ACH) {
        int b  = t / (KTOT / 8);
        int k0 = (t - b * (KTOT / 8)) * 8;
        const float* src = (k0 < DIN) ? (X + (size_t)b * DIN + k0)
                                      : (Hold + (size_t)b * H_ + (k0 - DIN));
        float4 v0 = __ldg((const float4*)src);
        float4 v1 = __ldg((const float4*)(src + 4));
        uint4 o;
        o.x = h2u(__floats2half2_rn(v0.x, v0.y));
        o.y = h2u(__floats2half2_rn(v0.z, v0.w));
        o.z = h2u(__floats2half2_rn(v1.x, v1.y));
        o.w = h2u(__floats2half2_rn(v1.z, v1.w));
        *(uint4*)(g_Ah + (size_t)b * KTOT + k0) = o;
    } else if (t < ACH + WCH) {
        int c0 = (t - ACH) * 8;
        int np = c0 / KTOT;
        int k0 = c0 - np * KTOT;
        int h, g; unpack_np(np, h, g);
        __half o[8];
        #pragma unroll
        for (int j = 0; j < 8; ++j) {
            int k = k0 + j;
            float v = (k < DIN) ? U[(g * DIN + k) * H_ + h]
                                : W[(g * H_ + (k - DIN)) * H_ + h];
            o[j] = __float2half_rn(v);
        }
        *(uint4*)(g_Wth + c0) = *(const uint4*)o;
    } else if (t < PACK_TOTAL) {
        int np = t - ACH - WCH;
        int h, g; unpack_np(np, h, g);
        g_bias[np] = bU[g * H_ + h] + bW[g * H_ + h];
    }
}

// ---------------- main fused kernel: 512 threads, 2 CTAs/SM (R10 base) ----------------
__global__ void __launch_bounds__(NTH, 2)
lstm_mma_kernel(const float* __restrict__ Cold, float* __restrict__ out) {
    extern __shared__ char smem[];
    const uint32_t sb = smem_u32(smem);
    const int tid = threadIdx.x;
    const int wid = tid >> 5, l = tid & 31;
    const int s = l & 7;
    const int hi4 = l >> 4;
    const int hi3 = (l >> 3) & 1;

    const int m0 = (int)(blockIdx.x >> 3) * BM;   // n-fastest for A L2 reuse
    const int n0 = (int)(blockIdx.x & 7) * BN;
    const int wm = wid >> 3, wn = wid & 7;        // 2 x 8 warps, each 64(m) x 32(n)

    // ---- ldmatrix row-base addresses + precomputed per-kc offsets ----
    uint32_t a_ld[4], b_ld[2], aoffs[4], boffs[4];
    #pragma unroll
    for (int mf = 0; mf < 4; ++mf)
        a_ld[mf] = sb + (uint32_t)((wm * 64 + mf * 16 + (l & 15)) * 128);
    #pragma unroll
    for (int p = 0; p < 2; ++p)
        b_ld[p] = sb + STG_A + (uint32_t)((wn * 32 + p * 16 + hi4 * 8 + (l & 7)) * 128);
    #pragma unroll
    for (int kc = 0; kc < 4; ++kc) {
        aoffs[kc] = (uint32_t)(((2 * kc + hi4) ^ s) << 4);
        boffs[kc] = (uint32_t)(((2 * kc + hi3) ^ s) << 4);
    }

    // ---- staging constants (512 threads) ----
    const int ar  = tid >> 2;            // A row 0..127, 4 threads/row
    const int ac0 = (tid & 3) * 2;       // 2 chunks of 16B each
    const int br  = tid >> 1;            // B row 0..255, 2 threads/row
    const int bc0 = (tid & 1) * 4;       // 4 chunks of 16B each
    uint32_t a_sdst[2], b_sdst[4];
    #pragma unroll
    for (int j = 0; j < 2; ++j)
        a_sdst[j] = sb + (uint32_t)ar * 128u + (uint32_t)(((ac0 + j) ^ (ar & 7)) << 4);
    #pragma unroll
    for (int j = 0; j < 4; ++j)
        b_sdst[j] = sb + STG_A + (uint32_t)br * 128u + (uint32_t)(((bc0 + j) ^ (br & 7)) << 4);
    const __half* a_srcb = g_Ah  + (size_t)(m0 + ar) * KTOT + ac0 * 8;
    const __half* b_srcb = g_Wth + (size_t)(n0 + br) * KTOT + bc0 * 8;

    auto stage_full = [&](uint32_t so, int it) {      // prologue only
        const __half* as = a_srcb + it * BKH;
        const __half* bs = b_srcb + it * BKH;
        #pragma unroll
        for (int j = 0; j < 2; ++j) cpasync16(a_sdst[j] + so, as + j * 8);
        #pragma unroll
        for (int j = 0; j < 4; ++j) cpasync16(b_sdst[j] + so, bs + j * 8);
        CP_COMMIT();
    };

    // ---- accumulators: fp16x2, [mf][nj][row-group] ----
    uint32_t C[4][4][2];
    #pragma unroll
    for (int mf = 0; mf < 4; ++mf)
        #pragma unroll
        for (int nj = 0; nj < 4; ++nj) { C[mf][nj][0] = 0u; C[mf][nj][1] = 0u; }

    // compute tile in `so`; interleave next tile's cp.asyncs between kc blocks
    // (2 after kc0, 2 after kc1, 2 after kc2, commit after kc3) to smooth the
    // L1/LSU port instead of bursting at iteration start.
    auto compute_pf = [&](uint32_t so, bool pf, uint32_t son, int itn) {
        const __half* asn = a_srcb + itn * BKH;       // folds under full unroll
        const __half* bsn = b_srcb + itn * BKH;
        #pragma unroll
        for (int kc = 0; kc < 4; ++kc) {
            uint32_t afr[4][4], bfr[2][4];
            #pragma unroll
            for (int mf = 0; mf < 4; ++mf) ldsm4(afr[mf], a_ld[mf] + so + aoffs[kc]);
            #pragma unroll
            for (int p = 0; p < 2; ++p)    ldsm4(bfr[p], b_ld[p] + so + boffs[kc]);
            #pragma unroll
            for (int mf = 0; mf < 4; ++mf)
                #pragma unroll
                for (int nj = 0; nj < 4; ++nj)
                    mma16816h(C[mf][nj], afr[mf], &bfr[nj >> 1][(nj & 1) * 2]);
            if (pf) {
                if (kc == 0) {
                    cpasync16(a_sdst[0] + son, asn);
                    cpasync16(a_sdst[1] + son, asn + 8);
                } else if (kc == 1) {
                    cpasync16(b_sdst[0] + son, bsn);
                    cpasync16(b_sdst[1] + son, bsn + 8);
                } else if (kc == 2) {
                    cpasync16(b_sdst[2] + son, bsn + 16);
                    cpasync16(b_sdst[3] + son, bsn + 24);
                } else {
                    CP_COMMIT();
                }
            }
        }
    };

    // ---- fully-unrolled 2-stage pipeline with in-compute staging ----
    stage_full(0, 0);
    #pragma unroll
    for (int it = 0; it < NIT; ++it) {
        asm volatile("cp.async.wait_group 0;" ::: "memory");
        __syncthreads();   // (a) tile `it` visible; (b) compute(it-1) reads done
        const bool pf = (it + 1 < NIT);
        compute_pf((it & 1) ? STG : 0u, pf, ((it + 1) & 1) ? STG : 0u, it + 1);
    }

    // ---- epilogue: four 32-row quarters through stage-0 smem (32 KB) ----
    // safe: last compute (it=11) reads stage 1 = [49152, 98304) only.
    const int q    = l & 3;
    const int quad = tid & 15;          // h-quad within CTA (16 quads = 64 h)
    const int r0   = tid >> 4;          // 0..31
    const int h0   = (n0 >> 2) + quad * 4;
    const int cb   = quad * 16;         // gate cols: [i x4, f x4, o x4, c x4]

    const float4 bi = __ldg((const float4*)(g_bias + n0 + cb));
    const float4 bf = __ldg((const float4*)(g_bias + n0 + cb + 4));
    const float4 bo = __ldg((const float4*)(g_bias + n0 + cb + 8));
    const float4 bc = __ldg((const float4*)(g_bias + n0 + cb + 12));

    #pragma unroll
    for (int qtr = 0; qtr < 4; ++qtr) {
        if (qtr) __syncthreads();       // previous quarter's pass-2 reads done
        // pass 1: owner warps dump their 2 mf-frag rows for this quarter
        if (wm == (qtr >> 1)) {
            #pragma unroll
            for (int mfl = 0; mfl < 2; ++mfl) {
                const int mf = 2 * (qtr & 1) + mfl;
                #pragma unroll
                for (int nj = 0; nj < 4; ++nj) {
                    const int cbase = wn * 32 + nj * 8 + 2 * q;
                    #pragma unroll
                    for (int dp = 0; dp < 2; ++dp) {
                        const int row = mfl * 16 + dp * 8 + (l >> 2);   // 0..31
                        float2 v = __half22float2(*reinterpret_cast<const __half2*>(&C[mf][nj][dp]));
                        sts_v2f(sb + gaddr(row, cbase), v.x, v.y);
                    }
                }
            }
        }
        __syncthreads();

        // pass 2: 512 threads fuse 32 rows x 64 h (one (row, h-quad) each)
        {
            const long long b = m0 + qtr * 32 + r0;

            float4 gi = lds_v4f(sb + gaddr(r0, cb));
            float4 gf = lds_v4f(sb + gaddr(r0, cb + 4));
            float4 go = lds_v4f(sb + gaddr(r0, cb + 8));
            float4 gc = lds_v4f(sb + gaddr(r0, cb + 12));
            float4 co = __ldg((const float4*)(Cold + b * H_ + h0));

            float4 hn, cn;
            {
                float i_ = sig_fast(gi.x + bi.x), f_ = sig_fast(gf.x + bf.x);
                float o_ = sig_fast(go.x + bo.x), ct = tanh_fast(gc.x + bc.x);
                cn.x = fmaf(i_, ct, f_ * co.x);  hn.x = o_ * tanh_fast(cn.x);
            }
            {
                float i_ = sig_fast(gi.y + bi.y), f_ = sig_fast(gf.y + bf.y);
                float o_ = sig_fast(go.y + bo.y), ct = tanh_fast(gc.y + bc.y);
                cn.y = fmaf(i_, ct, f_ * co.y);  hn.y = o_ * tanh_fast(cn.y);
            }
            {
                float i_ = sig_fast(gi.z + bi.z), f_ = sig_fast(gf.z + bf.z);
                float o_ = sig_fast(go.z + bo.z), ct = tanh_fast(gc.z + bc.z);
                cn.z = fmaf(i_, ct, f_ * co.z);  hn.z = o_ * tanh_fast(cn.z);
            }
            {
                float i_ = sig_fast(gi.w + bi.w), f_ = sig_fast(gf.w + bf.w);
                float o_ = sig_fast(go.w + bo.w), ct = tanh_fast(gc.w + bc.w);
                cn.w = fmaf(i_, ct, f_ * co.w);  hn.w = o_ * tanh_fast(cn.w);
            }

            *(float4*)(out + b * H_ + h0)      = hn;
            *(float4*)(out + BH + b * H_ + h0) = cn;
        }
    }
}

// ---------------- harness entry ----------------
extern "C" void kernel_launch(void* const* d_in, const int* in_sizes, int n_in,
                              void* d_out, int out_size) {
    const float* X    = (const float*)d_in[0];  // input_x [B, 256]
    const float* Hold = (const float*)d_in[1];  // h_old   [B, 512]
    const float* Cold = (const float*)d_in[2];  // c_old   [B, 512]
    const float* U    = (const float*)d_in[3];  // [4, 256, 512]
    const float* bU   = (const float*)d_in[4];  // [4, 512]
    const float* W    = (const float*)d_in[5];  // [4, 512, 512]
    const float* bW   = (const float*)d_in[6];  // [4, 512]
    float* out = (float*)d_out;                 // [h_new | c_new]
    (void)in_sizes; (void)n_in; (void)out_size;

    lstm_pack<<<(PACK_TOTAL + 255) / 256, 256>>>(U, bU, W, bW, X, Hold);

    cudaFuncSetAttribute(lstm_mma_kernel,
                         cudaFuncAttributeMaxDynamicSharedMemorySize, SMEM_BYTES);
    lstm_mma_kernel<<<GM * GN, NTH, SMEM_BYTES>>>(Cold, out);
}